// round 8
// baseline (speedup 1.0000x reference)
#include <cuda_runtime.h>
#include <cuda_fp16.h>
#include <cstdint>
#include <math.h>

#define NC      64
#define DHEAD   128
#define BATCHB  512
#define COLS    8192
#define NPAIRS  2016
#define KB      512          // fp8 bytes per column (K=512)
#define KC      64           // k-bytes per chunk  (fits PADB=80 row!)
#define NCH     8
#define PADB    80           // smem row stride: 64 data + 16 pad (20-word stride)
#define A_ST    (DHEAD * PADB)   // 10240
#define STAGE   (2 * A_ST)       // 20480

// fp16 of 256*q^2, transposed [gram][col][b]  (16.8 MB)
__device__ __half  g_Xh[2ULL * COLS * BATCHB];
// fp8 e4m3, per-column scaled to full range   (8.4 MB)
__device__ uint8_t g_X8[2ULL * COLS * BATCHB];
// per-column w = sqrt(max/448):  sqrt(G_true)*256 = sqrt(Ghat)*w_c*w_d
__device__ float   g_w[2ULL * COLS];
__device__ float   g_acc[4];

__device__ __forceinline__ float fsqrt_fast(float x) {
    float r; asm("sqrt.approx.f32 %0, %1;" : "=f"(r) : "f"(x)); return r;
}
#define CP16(dst, src) \
    asm volatile("cp.async.cg.shared.global [%0], [%1], 16;" :: "r"(dst), "l"(src))
#define CP_COMMIT() asm volatile("cp.async.commit_group;" ::: "memory")
#define CP_WAIT1()  asm volatile("cp.async.wait_group 1;"  ::: "memory")
#define CP_WAIT0()  asm volatile("cp.async.wait_group 0;"  ::: "memory")
__device__ __forceinline__ uint32_t smem_u32(const void* p) {
    uint32_t a;
    asm("{ .reg .u64 t; cvta.to.shared.u64 t, %1; cvt.u32.u64 %0, t; }" : "=r"(a) : "l"(p));
    return a;
}

// ---------------- kernel 0 ----------------
__global__ void k_zero() { if (threadIdx.x < 4) g_acc[threadIdx.x] = 0.0f; }

// ---------------- kernel 1: softmax -> fp16 256*q^2 transposed + self-sim dot ----------------
__global__ void k_softmax(const float* __restrict__ emb) {
    const int c    = blockIdx.y;
    const int b0   = blockIdx.x * 16;
    const int w    = threadIdx.x >> 5;
    const int lane = threadIdx.x & 31;

    __shared__ __align__(16) __half sm_t[2][DHEAD][16];
    __shared__ float dotred[16];

    const int b = b0 + w;
    const float* pa = emb + (size_t)b * COLS + c * DHEAD;
    const float* pb = emb + (size_t)(b + BATCHB) * COLS + c * DHEAD;

    float xa[4], xb[4];
#pragma unroll
    for (int p = 0; p < 4; ++p) { xa[p] = pa[lane + 32 * p]; xb[p] = pb[lane + 32 * p]; }

    float ma = fmaxf(fmaxf(xa[0], xa[1]), fmaxf(xa[2], xa[3]));
    float mb = fmaxf(fmaxf(xb[0], xb[1]), fmaxf(xb[2], xb[3]));
#pragma unroll
    for (int off = 16; off > 0; off >>= 1) {
        ma = fmaxf(ma, __shfl_xor_sync(0xFFFFFFFFu, ma, off));
        mb = fmaxf(mb, __shfl_xor_sync(0xFFFFFFFFu, mb, off));
    }
    float ea[4], eb[4], sa = 0.f, sb = 0.f;
#pragma unroll
    for (int p = 0; p < 4; ++p) {
        ea[p] = __expf(xa[p] - ma); sa += ea[p];
        eb[p] = __expf(xb[p] - mb); sb += eb[p];
    }
#pragma unroll
    for (int off = 16; off > 0; off >>= 1) {
        sa += __shfl_xor_sync(0xFFFFFFFFu, sa, off);
        sb += __shfl_xor_sync(0xFFFFFFFFu, sb, off);
    }
    const float ia = 16.0f / sa, ib = 16.0f / sb;
    float dot = 0.f;
#pragma unroll
    for (int p = 0; p < 4; ++p) {
        float qa = ea[p] * ia;
        float qb = eb[p] * ib;
        dot += qa * qb;                               // 256*qa*qb
        sm_t[0][lane + 32 * p][w] = __float2half_rn(qa * qa);   // 256*q^2
        sm_t[1][lane + 32 * p][w] = __float2half_rn(qb * qb);
    }
#pragma unroll
    for (int off = 16; off > 0; off >>= 1)
        dot += __shfl_xor_sync(0xFFFFFFFFu, dot, off);
    if (lane == 0) dotred[w] = dot;
    __syncthreads();
    if (threadIdx.x == 0) {
        float s = 0.f;
#pragma unroll
        for (int k = 0; k < 16; ++k) s += dotred[k];
        atomicAdd(&g_acc[0], s * (1.0f / 256.0f));
    }
    const int tid = threadIdx.x;
    const int g = tid >> 8;
    const int d = (tid >> 1) & 127;
    const int h = tid & 1;
    uint4 v = *(const uint4*)&sm_t[g][d][h * 8];
    __half* dst = g_Xh + (size_t)g * COLS * BATCHB
                + (size_t)(c * DHEAD + d) * BATCHB + (b0 + h * 8);
    *(uint4*)dst = v;
}

// ---------------- kernel 1b: per-column rescale fp16 -> e4m3 + w ----------------
__global__ void __launch_bounds__(256) k_scale() {
    const int wid  = threadIdx.x >> 5;
    const int lane = threadIdx.x & 31;
    const int gram = blockIdx.y;
    const int col  = blockIdx.x * 8 + wid;

    const __half* src = g_Xh + (size_t)gram * COLS * BATCHB + (size_t)col * BATCHB;
    uint8_t*      dst = g_X8 + (size_t)gram * COLS * BATCHB + (size_t)col * BATCHB;

    float v[16];
    const uint4 u0 = *(const uint4*)(src + lane * 16);
    const uint4 u1 = *(const uint4*)(src + lane * 16 + 8);
    const uint32_t hw[8] = {u0.x, u0.y, u0.z, u0.w, u1.x, u1.y, u1.z, u1.w};
#pragma unroll
    for (int k = 0; k < 8; ++k) {
        const __half2 h2 = *(const __half2*)&hw[k];
        const float2 f2 = __half22float2(h2);
        v[2 * k] = f2.x; v[2 * k + 1] = f2.y;
    }
    float mx = 0.f;
#pragma unroll
    for (int k = 0; k < 16; ++k) mx = fmaxf(mx, v[k]);
#pragma unroll
    for (int off = 16; off > 0; off >>= 1)
        mx = fmaxf(mx, __shfl_xor_sync(0xFFFFFFFFu, mx, off));
    mx = fmaxf(mx, 1e-30f);
    const float S = 448.0f / mx;
    if (lane == 0) g_w[(size_t)gram * COLS + col] = sqrtf(mx * (1.0f / 448.0f));

    uint32_t ob[4];
#pragma unroll
    for (int k = 0; k < 4; ++k) {
        uint16_t p0, p1;
        asm("cvt.rn.satfinite.e4m3x2.f32 %0, %1, %2;"
            : "=h"(p0) : "f"(v[4 * k + 1] * S), "f"(v[4 * k] * S));
        asm("cvt.rn.satfinite.e4m3x2.f32 %0, %1, %2;"
            : "=h"(p1) : "f"(v[4 * k + 3] * S), "f"(v[4 * k + 2] * S));
        ob[k] = (uint32_t)p0 | ((uint32_t)p1 << 16);
    }
    uint4 outv = {ob[0], ob[1], ob[2], ob[3]};
    *(uint4*)(dst + lane * 16) = outv;
}

// ---------------- kernel 2: 128x128 Gram tile, e4m3 QMMA, scaled-sqrt epilogue ----------
__global__ void __launch_bounds__(256, 2) k_gram(int gram) {
    __shared__ __align__(16) char sm[2 * STAGE];
    __shared__ float swr[DHEAD], swc[DHEAD];
    __shared__ float wsum[8];

    const uint32_t sbase = smem_u32(sm);
    const int tid  = threadIdx.x;
    const int wid  = tid >> 5;
    const int lane = tid & 31;

    const int t = blockIdx.x;
    int j = (int)((1.0f + sqrtf(8.0f * (float)t + 1.0f)) * 0.5f);
    while (j * (j - 1) / 2 > t) --j;
    while ((j + 1) * j / 2 <= t) ++j;
    const int i = t - j * (j - 1) / 2;

    const uint8_t* xg = g_X8 + (size_t)gram * COLS * BATCHB;
    const uint8_t* gA = xg + (size_t)j * DHEAD * BATCHB;
    const uint8_t* gB = xg + (size_t)i * DHEAD * BATCHB;

    if (tid < 128)       swr[tid]       = g_w[(size_t)gram * COLS + j * DHEAD + tid];
    else                 swc[tid - 128] = g_w[(size_t)gram * COLS + i * DHEAD + (tid - 128)];

    const int wr = (wid & 3) * 32;
    const int wc = (wid >> 2) * 64;
    const int g4 = lane >> 2;
    const int tg = lane & 3;

    float acc[2][8][4];
#pragma unroll
    for (int a = 0; a < 2; ++a)
#pragma unroll
        for (int b = 0; b < 8; ++b)
#pragma unroll
            for (int c2 = 0; c2 < 4; ++c2) acc[a][b][c2] = 0.f;

    // chunk = 128 rows x 64 bytes; 4 x 16B per row -> 512 cp.async per operand
    auto load_chunk = [&](int st, int ch) {
        const uint32_t aoff = sbase + st * STAGE;
        const uint32_t boff = aoff + A_ST;
#pragma unroll
        for (int it = 0; it < 2; ++it) {
            const int u = tid + it * 256;          // 0..511
            const int r = u >> 2, seg = u & 3;
            CP16(aoff + r * PADB + seg * 16, gA + (size_t)r * KB + ch * KC + seg * 16);
            CP16(boff + r * PADB + seg * 16, gB + (size_t)r * KB + ch * KC + seg * 16);
        }
        CP_COMMIT();
    };

    load_chunk(0, 0);

#pragma unroll 1
    for (int ch = 0; ch < NCH; ++ch) {
        const int st = ch & 1;
        if (ch + 1 < NCH) { load_chunk(st ^ 1, ch + 1); CP_WAIT1(); }
        else              { CP_WAIT0(); }
        __syncthreads();

        const char* pA = sm + st * STAGE;
        const char* pB = pA + A_ST;

#pragma unroll
        for (int ks = 0; ks < 2; ++ks) {           // K=64 bytes -> 2 x k32 mma
            const int k0 = ks * 32;
            uint32_t afr[2][4];
#pragma unroll
            for (int rm = 0; rm < 2; ++rm) {
                const int rb = wr + rm * 16;
                afr[rm][0] = *(const uint32_t*)(pA + (rb + g4     ) * PADB + k0 + tg * 4);
                afr[rm][1] = *(const uint32_t*)(pA + (rb + g4 + 8 ) * PADB + k0 + tg * 4);
                afr[rm][2] = *(const uint32_t*)(pA + (rb + g4     ) * PADB + k0 + tg * 4 + 16);
                afr[rm][3] = *(const uint32_t*)(pA + (rb + g4 + 8 ) * PADB + k0 + tg * 4 + 16);
            }
#pragma unroll
            for (int cn = 0; cn < 8; ++cn) {
                const int nb = wc + cn * 8;
                const uint32_t b0 = *(const uint32_t*)(pB + (nb + g4) * PADB + k0 + tg * 4);
                const uint32_t b1 = *(const uint32_t*)(pB + (nb + g4) * PADB + k0 + tg * 4 + 16);
#pragma unroll
                for (int rm = 0; rm < 2; ++rm) {
                    asm volatile(
                        "mma.sync.aligned.m16n8k32.row.col.f32.e4m3.e4m3.f32 "
                        "{%0,%1,%2,%3}, {%4,%5,%6,%7}, {%8,%9}, {%0,%1,%2,%3};"
                        : "+f"(acc[rm][cn][0]), "+f"(acc[rm][cn][1]),
                          "+f"(acc[rm][cn][2]), "+f"(acc[rm][cn][3])
                        : "r"(afr[rm][0]), "r"(afr[rm][1]), "r"(afr[rm][2]), "r"(afr[rm][3]),
                          "r"(b0), "r"(b1));
                }
            }
        }
        __syncthreads();
    }

    // epilogue: row = wr + rm*16 + g4 + 8*(c2>>1), col = wc + cn*8 + 2*tg + (c2&1)
    float lsum = 0.f;
#pragma unroll
    for (int rm = 0; rm < 2; ++rm) {
#pragma unroll
        for (int c2h = 0; c2h < 2; ++c2h) {
            const float wrv = swr[wr + rm * 16 + g4 + 8 * c2h];
#pragma unroll
            for (int cn = 0; cn < 8; ++cn) {
                const int cb = wc + cn * 8 + 2 * tg;
                lsum += fsqrt_fast(acc[rm][cn][2 * c2h    ]) * wrv * swc[cb    ];
                lsum += fsqrt_fast(acc[rm][cn][2 * c2h + 1]) * wrv * swc[cb + 1];
            }
        }
    }
#pragma unroll
    for (int off = 16; off > 0; off >>= 1)
        lsum += __shfl_xor_sync(0xFFFFFFFFu, lsum, off);
    if (lane == 0) wsum[wid] = lsum;
    __syncthreads();
    if (tid == 0) {
        float s = 0.f;
#pragma unroll
        for (int k = 0; k < 8; ++k) s += wsum[k];
        atomicAdd(&g_acc[1 + gram], s);
    }
}

// ---------------- kernel 3: finalize ----------------
__global__ void k_final(float* __restrict__ out) {
    // epilogue applied w_c*w_d -> acc = 256 * true sqrt-sum (i<j).
    const float scale = (float)(NC * NC - NC) * sqrtf((float)BATCHB);
    const float self = -g_acc[0] / (float)(BATCHB * NC);
    const float clus = -(2.0f * (g_acc[1] + g_acc[2]) / 256.0f) / (2.0f * scale);
    out[0] = self + clus;
}

extern "C" void kernel_launch(void* const* d_in, const int* in_sizes, int n_in,
                              void* d_out, int out_size) {
    const float* emb = (const float*)d_in[0];
    float* out = (float*)d_out;
    k_zero<<<1, 32>>>();
    k_softmax<<<dim3(32, 64), 512>>>(emb);
    k_scale<<<dim3(1024, 2), 256>>>();
    k_gram<<<NPAIRS, 256>>>(0);
    k_gram<<<NPAIRS, 256>>>(1);
    k_final<<<1, 1>>>(out);
}

// round 9
// speedup vs baseline: 1.1546x; 1.1546x over previous
#include <cuda_runtime.h>
#include <cuda_fp16.h>
#include <cstdint>
#include <math.h>

#define NC      64
#define DHEAD   128
#define BATCHB  512
#define COLS    8192
#define NPAIRS  2016
#define KC      64              // k-halfs per chunk (128B row)
#define NCH     8
#define PADH    72              // halfs per smem row (stride 144B, conflict-free)
#define ROWB    144
#define A_ST    (DHEAD * ROWB)  // 18432
#define STG     (2 * A_ST)      // 36864 per stage (A+B)
#define NSTG    3
#define SMEM_DYN (NSTG * STG)   // 110592

// fp16 of 256*q^2, transposed [gram][col][b]  (16.8 MB, L2-resident)
__device__ __half g_Xt[2ULL * COLS * BATCHB];
__device__ float  g_acc[4];

__device__ __forceinline__ float fsqrt_fast(float x) {
    float r; asm("sqrt.approx.f32 %0, %1;" : "=f"(r) : "f"(x)); return r;
}
__device__ __forceinline__ uint32_t smem_u32(const void* p) {
    uint32_t a;
    asm("{ .reg .u64 t; cvta.to.shared.u64 t, %1; cvt.u32.u64 %0, t; }" : "=r"(a) : "l"(p));
    return a;
}
#define CP16(dst, src) \
    asm volatile("cp.async.cg.shared.global [%0], [%1], 16;" :: "r"(dst), "l"(src))
#define CP_COMMIT() asm volatile("cp.async.commit_group;" ::: "memory")
#define CP_WAIT1()  asm volatile("cp.async.wait_group 1;"  ::: "memory")

// ---------------- kernel 0 ----------------
__global__ void k_zero() { if (threadIdx.x < 4) g_acc[threadIdx.x] = 0.0f; }

// ---------------- kernel 1: softmax -> fp16 256*q^2 transposed + self-sim dot ----------------
__global__ void k_softmax(const float* __restrict__ emb) {
    const int c    = blockIdx.y;
    const int b0   = blockIdx.x * 16;
    const int w    = threadIdx.x >> 5;
    const int lane = threadIdx.x & 31;

    __shared__ __align__(16) __half sm_t[2][DHEAD][16];
    __shared__ float dotred[16];

    const int b = b0 + w;
    const float* pa = emb + (size_t)b * COLS + c * DHEAD;
    const float* pb = emb + (size_t)(b + BATCHB) * COLS + c * DHEAD;

    float xa[4], xb[4];
#pragma unroll
    for (int p = 0; p < 4; ++p) { xa[p] = pa[lane + 32 * p]; xb[p] = pb[lane + 32 * p]; }

    float ma = fmaxf(fmaxf(xa[0], xa[1]), fmaxf(xa[2], xa[3]));
    float mb = fmaxf(fmaxf(xb[0], xb[1]), fmaxf(xb[2], xb[3]));
#pragma unroll
    for (int off = 16; off > 0; off >>= 1) {
        ma = fmaxf(ma, __shfl_xor_sync(0xFFFFFFFFu, ma, off));
        mb = fmaxf(mb, __shfl_xor_sync(0xFFFFFFFFu, mb, off));
    }
    float ea[4], eb[4], sa = 0.f, sb = 0.f;
#pragma unroll
    for (int p = 0; p < 4; ++p) {
        ea[p] = __expf(xa[p] - ma); sa += ea[p];
        eb[p] = __expf(xb[p] - mb); sb += eb[p];
    }
#pragma unroll
    for (int off = 16; off > 0; off >>= 1) {
        sa += __shfl_xor_sync(0xFFFFFFFFu, sa, off);
        sb += __shfl_xor_sync(0xFFFFFFFFu, sb, off);
    }
    const float ia = 16.0f / sa, ib = 16.0f / sb;
    float dot = 0.f;
#pragma unroll
    for (int p = 0; p < 4; ++p) {
        float qa = ea[p] * ia;
        float qb = eb[p] * ib;
        dot += qa * qb;                               // 256*qa*qb
        sm_t[0][lane + 32 * p][w] = __float2half_rn(qa * qa);   // 256*q^2
        sm_t[1][lane + 32 * p][w] = __float2half_rn(qb * qb);
    }
#pragma unroll
    for (int off = 16; off > 0; off >>= 1)
        dot += __shfl_xor_sync(0xFFFFFFFFu, dot, off);
    if (lane == 0) dotred[w] = dot;
    __syncthreads();
    if (threadIdx.x == 0) {
        float s = 0.f;
#pragma unroll
        for (int k = 0; k < 16; ++k) s += dotred[k];
        atomicAdd(&g_acc[0], s * (1.0f / 256.0f));
    }
    const int tid = threadIdx.x;
    const int g = tid >> 8;
    const int d = (tid >> 1) & 127;
    const int h = tid & 1;
    uint4 v = *(const uint4*)&sm_t[g][d][h * 8];
    __half* dst = g_Xt + (size_t)g * COLS * BATCHB
                + (size_t)(c * DHEAD + d) * BATCHB + (b0 + h * 8);
    *(uint4*)dst = v;
}

// ---------------- kernel 2: 128x128 Gram tile, HMMA, 3-stage cp.async ----------------
// 8 warps 4(row)x2(col), warp tile 32x64, mma m16n8k16 f16->f32, K=512 in 8 chunks.
__global__ void __launch_bounds__(256, 2) k_gram(int gram) {
    extern __shared__ __align__(16) char dsm[];
    __shared__ float wsum[8];

    const uint32_t sbase = smem_u32(dsm);
    const int tid  = threadIdx.x;
    const int wid  = tid >> 5;
    const int lane = tid & 31;

    // pair decode: t = j*(j-1)/2 + i, i < j
    const int t = blockIdx.x;
    int j = (int)((1.0f + sqrtf(8.0f * (float)t + 1.0f)) * 0.5f);
    while (j * (j - 1) / 2 > t) --j;
    while ((j + 1) * j / 2 <= t) ++j;
    const int i = t - j * (j - 1) / 2;

    const __half* xg = g_Xt + (size_t)gram * COLS * BATCHB;
    const __half* gA = xg + (size_t)j * DHEAD * BATCHB;
    const __half* gB = xg + (size_t)i * DHEAD * BATCHB;

    const int wr = (wid & 3) * 32;
    const int wc = (wid >> 2) * 64;
    const int g4 = lane >> 5 ? 0 : (lane >> 2);   // lane>>2 (0..7)
    const int tg = lane & 3;

    float acc[2][8][4];
#pragma unroll
    for (int a = 0; a < 2; ++a)
#pragma unroll
        for (int b = 0; b < 8; ++b)
#pragma unroll
            for (int c2 = 0; c2 < 4; ++c2) acc[a][b][c2] = 0.f;

    // chunk loader: 128 rows x 64 halfs per operand -> 8 cp.async per thread
    auto load_chunk = [&](int st, int ch) {
        const uint32_t aoff = sbase + st * STG;
        const uint32_t boff = aoff + A_ST;
#pragma unroll
        for (int it = 0; it < 4; ++it) {
            const int u = tid + it * 256;           // 0..1023
            const int r = u >> 3, seg = u & 7;
            const size_t goff = (size_t)r * BATCHB + ch * KC + seg * 8;
            CP16(aoff + r * ROWB + seg * 16, gA + goff);
            CP16(boff + r * ROWB + seg * 16, gB + goff);
        }
        CP_COMMIT();
    };

    load_chunk(0, 0);
    load_chunk(1, 1);

#pragma unroll 1
    for (int ch = 0; ch < NCH; ++ch) {
        const int st = ch % NSTG;
        CP_WAIT1();                 // group ch complete (newest may stay pending)
        __syncthreads();

        const char* pA = dsm + st * STG;
        const char* pB = pA + A_ST;

#pragma unroll
        for (int ks = 0; ks < 4; ++ks) {            // 4 x k16 per chunk
            const int k0 = ks * 16;
            uint32_t afr[2][4];
#pragma unroll
            for (int rm = 0; rm < 2; ++rm) {
                const int rb = wr + rm * 16;
                afr[rm][0] = *(const uint32_t*)(pA + (rb + g4     ) * ROWB + (k0 + tg * 2    ) * 2);
                afr[rm][1] = *(const uint32_t*)(pA + (rb + g4 + 8 ) * ROWB + (k0 + tg * 2    ) * 2);
                afr[rm][2] = *(const uint32_t*)(pA + (rb + g4     ) * ROWB + (k0 + tg * 2 + 8) * 2);
                afr[rm][3] = *(const uint32_t*)(pA + (rb + g4 + 8 ) * ROWB + (k0 + tg * 2 + 8) * 2);
            }
#pragma unroll
            for (int cn = 0; cn < 8; ++cn) {
                const int nb = wc + cn * 8;
                const uint32_t b0 = *(const uint32_t*)(pB + (nb + g4) * ROWB + (k0 + tg * 2    ) * 2);
                const uint32_t b1 = *(const uint32_t*)(pB + (nb + g4) * ROWB + (k0 + tg * 2 + 8) * 2);
#pragma unroll
                for (int rm = 0; rm < 2; ++rm) {
                    asm volatile(
                        "mma.sync.aligned.m16n8k16.row.col.f32.f16.f16.f32 "
                        "{%0,%1,%2,%3}, {%4,%5,%6,%7}, {%8,%9}, {%0,%1,%2,%3};"
                        : "+f"(acc[rm][cn][0]), "+f"(acc[rm][cn][1]),
                          "+f"(acc[rm][cn][2]), "+f"(acc[rm][cn][3])
                        : "r"(afr[rm][0]), "r"(afr[rm][1]), "r"(afr[rm][2]), "r"(afr[rm][3]),
                          "r"(b0), "r"(b1));
                }
            }
        }
        // prefetch 2 chunks ahead into stage (ch+2)%3 — never read by iters ch / ch+1
        if (ch + 2 < NCH) load_chunk((ch + 2) % NSTG, ch + 2);
    }

    // epilogue: sum sqrt over all accumulator entries
    float lsum = 0.f;
#pragma unroll
    for (int a = 0; a < 2; ++a)
#pragma unroll
        for (int b = 0; b < 8; ++b)
#pragma unroll
            for (int c2 = 0; c2 < 4; ++c2) lsum += fsqrt_fast(acc[a][b][c2]);
#pragma unroll
    for (int off = 16; off > 0; off >>= 1)
        lsum += __shfl_xor_sync(0xFFFFFFFFu, lsum, off);
    if (lane == 0) wsum[wid] = lsum;
    __syncthreads();
    if (tid == 0) {
        float s = 0.f;
#pragma unroll
        for (int k = 0; k < 8; ++k) s += wsum[k];
        atomicAdd(&g_acc[1 + gram], s);
    }
}

// ---------------- kernel 3: finalize ----------------
__global__ void k_final(float* __restrict__ out) {
    // operands 256*q^2 -> G x65536 -> sqrt x256. raw_g (i!=j) = 2*acc/256.
    const float scale = (float)(NC * NC - NC) * sqrtf((float)BATCHB);
    const float self = -g_acc[0] / (float)(BATCHB * NC);
    const float clus = -(2.0f * (g_acc[1] + g_acc[2]) / 256.0f) / (2.0f * scale);
    out[0] = self + clus;
}

extern "C" void kernel_launch(void* const* d_in, const int* in_sizes, int n_in,
                              void* d_out, int out_size) {
    const float* emb = (const float*)d_in[0];
    float* out = (float*)d_out;
    cudaFuncSetAttribute(k_gram, cudaFuncAttributeMaxDynamicSharedMemorySize, SMEM_DYN);
    k_zero<<<1, 32>>>();
    k_softmax<<<dim3(32, 64), 512>>>(emb);
    k_gram<<<NPAIRS, 256, SMEM_DYN>>>(0);
    k_gram<<<NPAIRS, 256, SMEM_DYN>>>(1);
    k_final<<<1, 1>>>(out);
}